// round 15
// baseline (speedup 1.0000x reference)
#include <cuda_runtime.h>
#include <cstdint>

// Problem constants
#define BATCH 8
#define SEQ   4
#define DMODEL 2048
#define NHEAD 32
#define HDIM  64
#define CACHE 4096
#define MROWS (BATCH * SEQ)   // 32
#define SPLIT 4
#define KPB   1024            // cache keys per attention block
#define QKV_SPLIT 8
#define WO_SPLIT  16
#define NST   3               // cp.async pipeline depth

// ---------------- scratch (device globals; no allocation allowed) -------------
static __device__ float g_attn[MROWS * DMODEL];
static __device__ float g_qkvp[3][QKV_SPLIT][MROWS * DMODEL];
static __device__ float g_part[WO_SPLIT][MROWS * DMODEL];
static __device__ float g_po[BATCH * NHEAD * SPLIT * SEQ * HDIM];
static __device__ float g_s [BATCH * NHEAD * SPLIT * SEQ];

// ---------------- f32x2 helpers -----------------------------------------------
__device__ __forceinline__ void ffma2(unsigned long long& d,
                                      unsigned long long a,
                                      unsigned long long b)
{
    asm volatile("fma.rn.f32x2 %0, %1, %2, %0;" : "+l"(d) : "l"(a), "l"(b));
}
__device__ __forceinline__ float2 unpack2(unsigned long long u)
{
    float2 r;
    asm volatile("mov.b64 {%0, %1}, %2;" : "=f"(r.x), "=f"(r.y) : "l"(u));
    return r;
}
__device__ __forceinline__ unsigned long long pack2(float a, float b)
{
    unsigned long long u;
    asm volatile("mov.b64 %0, {%1, %2};" : "=l"(u) : "f"(a), "f"(b));
    return u;
}
union F4 { float4 v; unsigned long long u[2]; };

__device__ __forceinline__ void cp16(uint32_t smem_addr, const float* gptr)
{
    asm volatile("cp.async.cg.shared.global [%0], [%1], 16;"
                 :: "r"(smem_addr), "l"(gptr));
}
__device__ __forceinline__ void cp_commit()
{
    asm volatile("cp.async.commit_group;");
}
__device__ __forceinline__ void cp_wait2()
{
    asm volatile("cp.async.wait_group 2;");
}

// ==============================================================================
// GEMM v4 (round-10 proven): cp.async 3-stage pipelined, stages of 32 k.
// ==============================================================================
__device__ __forceinline__ void gemm_pipe(
    const float* __restrict__ X, const float* __restrict__ W,
    float* __restrict__ out, int tile, int kbeg, int nstages)
{
    __shared__ __align__(16) float Xs[NST][32 * 36];
    __shared__ __align__(16) float Ws[NST][64 * 36];

    const int tid = threadIdx.x;
    const int tx = tid & 31;
    const int ty = tid >> 5;

    const int xrow = tid >> 3, xc4 = tid & 7;
    const uint32_t xs_a = (uint32_t)__cvta_generic_to_shared(
        &Xs[0][xrow * 36 + xc4 * 4]);
    const float* xg = X + (size_t)xrow * DMODEL + kbeg + xc4 * 4;

    uint32_t ws_a[2];
    const float* wg[2];
#pragma unroll
    for (int i = 0; i < 2; i++) {
        const int fid = i * 256 + tid;
        const int wrow = fid >> 3, wc4 = fid & 7;
        ws_a[i] = (uint32_t)__cvta_generic_to_shared(
            &Ws[0][wrow * 36 + wc4 * 4]);
        wg[i] = W + (size_t)(tile * 64 + wrow) * DMODEL + kbeg + wc4 * 4;
    }
    const uint32_t XBUF = 32 * 36 * 4;
    const uint32_t WBUF = 64 * 36 * 4;

    unsigned long long acc[4][2];
#pragma unroll
    for (int i = 0; i < 4; i++) { acc[i][0] = 0ull; acc[i][1] = 0ull; }

#pragma unroll
    for (int s = 0; s < NST; s++) {
        cp16(xs_a + s * XBUF, xg + s * 32);
        cp16(ws_a[0] + s * WBUF, wg[0] + s * 32);
        cp16(ws_a[1] + s * WBUF, wg[1] + s * 32);
        cp_commit();
    }

    for (int st = 0; st < nstages; ++st) {
        const int buf = st % NST;
        cp_wait2();
        __syncthreads();

        const float* xb = Xs[buf];
        const float* wb = Ws[buf];
#pragma unroll
        for (int kk = 0; kk < 32; kk += 8) {
            F4 w00, w01, w10, w11;
            w00.v = *(const float4*)(wb + tx * 36 + kk);
            w01.v = *(const float4*)(wb + tx * 36 + kk + 4);
            w10.v = *(const float4*)(wb + (tx + 32) * 36 + kk);
            w11.v = *(const float4*)(wb + (tx + 32) * 36 + kk + 4);
#pragma unroll
            for (int i = 0; i < 4; i++) {
                F4 xa, xc;
                xa.v = *(const float4*)(xb + (ty * 4 + i) * 36 + kk);
                xc.v = *(const float4*)(xb + (ty * 4 + i) * 36 + kk + 4);
                ffma2(acc[i][0], xa.u[0], w00.u[0]);
                ffma2(acc[i][0], xa.u[1], w00.u[1]);
                ffma2(acc[i][0], xc.u[0], w01.u[0]);
                ffma2(acc[i][0], xc.u[1], w01.u[1]);
                ffma2(acc[i][1], xa.u[0], w10.u[0]);
                ffma2(acc[i][1], xa.u[1], w10.u[1]);
                ffma2(acc[i][1], xc.u[0], w11.u[0]);
                ffma2(acc[i][1], xc.u[1], w11.u[1]);
            }
        }
        __syncthreads();

        const int nx = st + NST;
        if (nx < nstages) {
            cp16(xs_a + buf * XBUF, xg + nx * 32);
            cp16(ws_a[0] + buf * WBUF, wg[0] + nx * 32);
            cp16(ws_a[1] + buf * WBUF, wg[1] + nx * 32);
        }
        cp_commit();
    }

#pragma unroll
    for (int i = 0; i < 4; i++) {
#pragma unroll
        for (int j = 0; j < 2; j++) {
            const float2 h2 = unpack2(acc[i][j]);
            out[(size_t)(ty * 4 + i) * DMODEL + tile * 64 + tx + j * 32] =
                h2.x + h2.y;
        }
    }
}

// qkv: grid 768 = 3 mats x 8 splits x 32 tiles; 8 stages of 32 k per block
__global__ void __launch_bounds__(256, 3) qkv_gemm_kernel(
    const float* __restrict__ x,
    const float* __restrict__ wq, const float* __restrict__ wk,
    const float* __restrict__ wv)
{
    const int tile = blockIdx.x & 31;
    const int ks   = (blockIdx.x >> 5) & 7;
    const int g    = blockIdx.x >> 8;
    const float* W = (g == 0) ? wq : (g == 1 ? wk : wv);
    gemm_pipe(x, W, g_qkvp[g][ks], tile, ks * 256, 8);
}

// wo: grid 512 = 16 splits x 32 tiles; 4 stages of 32 k per block
__global__ void __launch_bounds__(256, 3) wo_gemm_kernel(const float* __restrict__ wo)
{
    const int ks = blockIdx.x >> 5;
    const int tile = blockIdx.x & 31;
    gemm_pipe(g_attn, wo, g_part[ks], tile, ks * 128, 4);
}

__global__ void __launch_bounds__(256) combine_kernel(float* __restrict__ out)
{
    const int i = blockIdx.x * 256 + threadIdx.x;
    float r = 0.f;
#pragma unroll
    for (int ks = 0; ks < WO_SPLIT; ks++) r += g_part[ks][i];
    out[i] = r;
}

// ==============================================================================
// Attention v9: SPLIT=4 (1024 keys/block), warp strip = 128 keys processed as
//   2 halves of the proven 16-round PF2 fused loop. No-max softmax.
// ==============================================================================
__global__ void __launch_bounds__(256, 2) attn_kernel(
    const float* __restrict__ ck, const float* __restrict__ cv,
    const float* __restrict__ fc, const float* __restrict__ fs)
{
    __shared__ __align__(16) float qs[4 * 68];
    __shared__ __align__(16) float kxs[4 * 68];
    __shared__ __align__(16) float vxs[4 * 68];
    __shared__ __align__(16) float avred[8 * 256];
    __shared__ __align__(16) float red[40];
    __shared__ __align__(16) float scnew[16];

    const int bh    = blockIdx.x >> 2;
    const int split = blockIdx.x & 3;
    const int b = bh >> 5;
    const int h = bh & 31;
    const int tid = threadIdx.x;
    const int kbase = split * KPB;
    const int wid = tid >> 5, lane = tid & 31;

    // prologue: combine qkv partials + RoPE
    if (tid < 128) {
        const int s = tid >> 5, p = tid & 31;
        const size_t off = (size_t)(b * SEQ + s) * DMODEL + h * HDIM + 2 * p;
        float2 e = *(const float2*)(&g_qkvp[0][0][off]);
#pragma unroll
        for (int ks = 1; ks < QKV_SPLIT; ks++) {
            const float2 t = *(const float2*)(&g_qkvp[0][ks][off]);
            e.x += t.x; e.y += t.y;
        }
        const float c  = fc[s * 32 + p];
        const float sn = fs[s * 32 + p];
        qs[s * 68 + 2 * p]     = (e.x * c - e.y * sn) * 0.125f;
        qs[s * 68 + 2 * p + 1] = (e.x * sn + e.y * c) * 0.125f;
    } else if (split == SPLIT - 1) {
        const int t2 = tid - 128;
        const int s = t2 >> 5, p = t2 & 31;
        const size_t off = (size_t)(b * SEQ + s) * DMODEL + h * HDIM + 2 * p;
        float2 e = *(const float2*)(&g_qkvp[1][0][off]);
#pragma unroll
        for (int ks = 1; ks < QKV_SPLIT; ks++) {
            const float2 t = *(const float2*)(&g_qkvp[1][ks][off]);
            e.x += t.x; e.y += t.y;
        }
        const float c  = fc[s * 32 + p];
        const float sn = fs[s * 32 + p];
        kxs[s * 68 + 2 * p]     = e.x * c - e.y * sn;
        kxs[s * 68 + 2 * p + 1] = e.x * sn + e.y * c;
        float2 v = *(const float2*)(&g_qkvp[2][0][off]);
#pragma unroll
        for (int ks = 1; ks < QKV_SPLIT; ks++) {
            const float2 t = *(const float2*)(&g_qkvp[2][ks][off]);
            v.x += t.x; v.y += t.y;
        }
        vxs[s * 68 + 2 * p]     = v.x;
        vxs[s * 68 + 2 * p + 1] = v.y;
    }
    __syncthreads();

    const int g = lane >> 3;
    const int s = lane & 7;

    F4 qr[4][2];
#pragma unroll
    for (int qi = 0; qi < 4; qi++) {
        qr[qi][0].v = *(const float4*)(qs + qi * 68 + s * 4);
        qr[qi][1].v = *(const float4*)(qs + qi * 68 + s * 4 + 32);
    }

    const size_t rs = NHEAD * HDIM;
    const size_t rowoff = ((size_t)b * CACHE * NHEAD + h) * HDIM
                        + (size_t)(kbase + wid * 128 + g) * rs + s * 4;

    unsigned long long acc[4][4];
#pragma unroll
    for (int q = 0; q < 4; q++)
#pragma unroll
        for (int j = 0; j < 4; j++) acc[q][j] = 0ull;
    float ssum = 0.f;

    // warp strip = 128 keys: 2 halves x 16 rounds (PF2 triple-buffered)
    for (int half = 0; half < 2; half++) {
        const float* kp = ck + rowoff + (size_t)(half * 64) * rs;
        const float* vp = cv + rowoff + (size_t)(half * 64) * rs;

        F4 kA[3][2], vA[3][2];
#pragma unroll
        for (int r = 0; r < 2; r++) {
            const float* kn = kp + (size_t)r * 4 * rs;
            const float* vn = vp + (size_t)r * 4 * rs;
            kA[r][0].v = *(const float4*)(kn);
            kA[r][1].v = *(const float4*)(kn + 32);
            vA[r][0].v = *(const float4*)(vn);
            vA[r][1].v = *(const float4*)(vn + 32);
        }

#pragma unroll
        for (int r = 0; r < 16; r++) {
            const int cur = r % 3;
            if (r + 2 < 16) {
                const int nxt = (r + 2) % 3;
                const float* kn = kp + (size_t)(r + 2) * 4 * rs;
                const float* vn = vp + (size_t)(r + 2) * 4 * rs;
                kA[nxt][0].v = *(const float4*)(kn);
                kA[nxt][1].v = *(const float4*)(kn + 32);
                vA[nxt][0].v = *(const float4*)(vn);
                vA[nxt][1].v = *(const float4*)(vn + 32);
            }

            float p0, p1, p2, p3;
            {
                unsigned long long a = 0ull;
                ffma2(a, kA[cur][0].u[0], qr[0][0].u[0]); ffma2(a, kA[cur][0].u[1], qr[0][0].u[1]);
                ffma2(a, kA[cur][1].u[0], qr[0][1].u[0]); ffma2(a, kA[cur][1].u[1], qr[0][1].u[1]);
                const float2 t = unpack2(a); p0 = t.x + t.y;
            }
            {
                unsigned long long a = 0ull;
                ffma2(a, kA[cur][0].u[0], qr[1][0].u[0]); ffma2(a, kA[cur][0].u[1], qr[1][0].u[1]);
                ffma2(a, kA[cur][1].u[0], qr[1][1].u[0]); ffma2(a, kA[cur][1].u[1], qr[1][1].u[1]);
                const float2 t = unpack2(a); p1 = t.x + t.y;
            }
            {
                unsigned long long a = 0ull;
                ffma2(a, kA[cur][0].u[0], qr[2][0].u[0]); ffma2(a, kA[cur][0].u[1], qr[2][0].u[1]);
                ffma2(a, kA[cur][1].u[0], qr[2][1].u[0]); ffma2(a, kA[cur][1].u[1], qr[2][1].u[1]);
                const float2 t = unpack2(a); p2 = t.x + t.y;
            }
            {
                unsigned long long a = 0ull;
                ffma2(a, kA[cur][0].u[0], qr[3][0].u[0]); ffma2(a, kA[cur][0].u[1], qr[3][0].u[1]);
                ffma2(a, kA[cur][1].u[0], qr[3][1].u[0]); ffma2(a, kA[cur][1].u[1], qr[3][1].u[1]);
                const float2 t = unpack2(a); p3 = t.x + t.y;
            }
#pragma unroll
            for (int o = 1; o <= 4; o <<= 1) {
                p0 += __shfl_xor_sync(0xffffffffu, p0, o);
                p1 += __shfl_xor_sync(0xffffffffu, p1, o);
                p2 += __shfl_xor_sync(0xffffffffu, p2, o);
                p3 += __shfl_xor_sync(0xffffffffu, p3, o);
            }
            const float e0 = __expf(p0);
            const float e1 = __expf(p1);
            const float e2 = __expf(p2);
            const float e3 = __expf(p3);
            {
                const float pa = (s & 1) ? e1 : e0;
                const float pb = (s & 1) ? e3 : e2;
                if (s < 4) ssum += (s & 2) ? pb : pa;
            }
            {
                const unsigned long long ee0 = pack2(e0, e0);
                const unsigned long long ee1 = pack2(e1, e1);
                const unsigned long long ee2 = pack2(e2, e2);
                const unsigned long long ee3 = pack2(e3, e3);
                ffma2(acc[0][0], vA[cur][0].u[0], ee0); ffma2(acc[0][1], vA[cur][0].u[1], ee0);
                ffma2(acc[0][2], vA[cur][1].u[0], ee0); ffma2(acc[0][3], vA[cur][1].u[1], ee0);
                ffma2(acc[1][0], vA[cur][0].u[0], ee1); ffma2(acc[1][1], vA[cur][0].u[1], ee1);
                ffma2(acc[1][2], vA[cur][1].u[0], ee1); ffma2(acc[1][3], vA[cur][1].u[1], ee1);
                ffma2(acc[2][0], vA[cur][0].u[0], ee2); ffma2(acc[2][1], vA[cur][0].u[1], ee2);
                ffma2(acc[2][2], vA[cur][1].u[0], ee2); ffma2(acc[2][3], vA[cur][1].u[1], ee2);
                ffma2(acc[3][0], vA[cur][0].u[0], ee3); ffma2(acc[3][1], vA[cur][0].u[1], ee3);
                ffma2(acc[3][2], vA[cur][1].u[0], ee3); ffma2(acc[3][3], vA[cur][1].u[1], ee3);
            }
        }
    }

#pragma unroll
    for (int q = 0; q < 4; q++) {
        float o0 = unpack2(acc[q][0]).x, o1 = unpack2(acc[q][0]).y;
        float o2 = unpack2(acc[q][1]).x, o3 = unpack2(acc[q][1]).y;
        float o4 = unpack2(acc[q][2]).x, o5 = unpack2(acc[q][2]).y;
        float o6 = unpack2(acc[q][3]).x, o7 = unpack2(acc[q][3]).y;
#pragma unroll
        for (int o = 8; o <= 16; o <<= 1) {
            o0 += __shfl_xor_sync(0xffffffffu, o0, o);
            o1 += __shfl_xor_sync(0xffffffffu, o1, o);
            o2 += __shfl_xor_sync(0xffffffffu, o2, o);
            o3 += __shfl_xor_sync(0xffffffffu, o3, o);
            o4 += __shfl_xor_sync(0xffffffffu, o4, o);
            o5 += __shfl_xor_sync(0xffffffffu, o5, o);
            o6 += __shfl_xor_sync(0xffffffffu, o6, o);
            o7 += __shfl_xor_sync(0xffffffffu, o7, o);
        }
        if (g == 0) {
            *(float4*)(avred + wid * 256 + q * 64 + s * 4) =
                make_float4(o0, o1, o2, o3);
            *(float4*)(avred + wid * 256 + q * 64 + 32 + s * 4) =
                make_float4(o4, o5, o6, o7);
        }
    }
    ssum += __shfl_xor_sync(0xffffffffu, ssum, 8);
    ssum += __shfl_xor_sync(0xffffffffu, ssum, 16);
    if (lane < 4) red[wid * 4 + lane] = ssum;

    if (split == SPLIT - 1) {
        if (tid < 16) {
            const int q = tid >> 2, j = tid & 3;
            float a = 0.f;
#pragma unroll
            for (int d = 0; d < HDIM; d++) a += qs[q * 68 + d] * kxs[j * 68 + d];
            scnew[j * 4 + q] = (j > q) ? 0.f : __expf(a);
        }
    } else if (tid < 16) {
        scnew[tid] = 0.f;
    }
    __syncthreads();

    if (tid < 4) {
        float t = 0.f;
#pragma unroll
        for (int w = 0; w < 8; w++) t += red[w * 4 + tid];
#pragma unroll
        for (int j = 0; j < SEQ; j++) t += scnew[j * 4 + tid];
        red[32 + tid] = t;
    }
    __syncthreads();

    // write this split's unnormalized partial + s
    {
        const int q = tid >> 6, d = tid & 63;
        float r = 0.f;
#pragma unroll
        for (int w = 0; w < 8; w++) r += avred[w * 256 + q * 64 + d];
        if (split == SPLIT - 1) {
#pragma unroll
            for (int j = 0; j < SEQ; j++)
                r += scnew[j * 4 + q] * vxs[j * 68 + d];
        }
        const int base = (bh * SPLIT + split) * SEQ + q;
        g_po[(size_t)base * HDIM + d] = r;
        if (d == 0) g_s[base] = red[32 + q];
    }
}

// merge the 4 split partials per (b, h): pure sum
__global__ void __launch_bounds__(256) attn_combine_kernel()
{
    const int bh = blockIdx.x;
    const int tid = threadIdx.x;
    const int q = tid >> 6, d = tid & 63;

    float num = 0.f, den = 0.f;
#pragma unroll
    for (int i = 0; i < SPLIT; i++) {
        const int base = (bh * SPLIT + i) * SEQ + q;
        num += g_po[(size_t)base * HDIM + d];
        den += g_s[base];
    }
    const int b = bh >> 5, h = bh & 31;
    g_attn[(size_t)(b * SEQ + q) * DMODEL + h * HDIM + d] = num / den;
}

// ==============================================================================
extern "C" void kernel_launch(void* const* d_in, const int* in_sizes, int n_in,
                              void* d_out, int out_size)
{
    const float* x  = (const float*)d_in[0];
    const float* fc = (const float*)d_in[1];
    const float* fs = (const float*)d_in[2];
    const float* ck = (const float*)d_in[4];
    const float* cv = (const float*)d_in[5];
    const float* wq = (const float*)d_in[6];
    const float* wk = (const float*)d_in[7];
    const float* wv = (const float*)d_in[8];
    const float* wo = (const float*)d_in[9];
    float* out = (float*)d_out;

    qkv_gemm_kernel<<<3 * QKV_SPLIT * 32, 256>>>(x, wq, wk, wv);
    attn_kernel<<<BATCH * NHEAD * SPLIT, 256>>>(ck, cv, fc, fs);
    attn_combine_kernel<<<BATCH * NHEAD, 256>>>();
    wo_gemm_kernel<<<WO_SPLIT * 32, 256>>>(wo);
    combine_kernel<<<MROWS * DMODEL / 256, 256>>>(out);
}

// round 16
// speedup vs baseline: 1.0306x; 1.0306x over previous
#include <cuda_runtime.h>
#include <cstdint>

// Problem constants
#define BATCH 8
#define SEQ   4
#define DMODEL 2048
#define NHEAD 32
#define HDIM  64
#define CACHE 4096
#define MROWS (BATCH * SEQ)   // 32
#define SPLIT 8
#define KPB   512             // cache keys per attention block
#define QKV_SPLIT 8
#define WO_SPLIT  16
#define NST   2               // cp.async pipeline depth (64-k stages)

// ---------------- scratch (device globals; no allocation allowed) -------------
static __device__ float g_attn[MROWS * DMODEL];
static __device__ float g_qkvp[3][QKV_SPLIT][MROWS * DMODEL];
static __device__ float g_part[WO_SPLIT][MROWS * DMODEL];
static __device__ float g_po[BATCH * NHEAD * SPLIT * SEQ * HDIM];
static __device__ float g_s [BATCH * NHEAD * SPLIT * SEQ];

// ---------------- f32x2 helpers -----------------------------------------------
__device__ __forceinline__ void ffma2(unsigned long long& d,
                                      unsigned long long a,
                                      unsigned long long b)
{
    asm volatile("fma.rn.f32x2 %0, %1, %2, %0;" : "+l"(d) : "l"(a), "l"(b));
}
__device__ __forceinline__ float2 unpack2(unsigned long long u)
{
    float2 r;
    asm volatile("mov.b64 {%0, %1}, %2;" : "=f"(r.x), "=f"(r.y) : "l"(u));
    return r;
}
__device__ __forceinline__ unsigned long long pack2(float a, float b)
{
    unsigned long long u;
    asm volatile("mov.b64 %0, {%1, %2};" : "=l"(u) : "f"(a), "f"(b));
    return u;
}
union F4 { float4 v; unsigned long long u[2]; };

__device__ __forceinline__ void cp16(uint32_t smem_addr, const float* gptr)
{
    asm volatile("cp.async.cg.shared.global [%0], [%1], 16;"
                 :: "r"(smem_addr), "l"(gptr));
}
__device__ __forceinline__ void cp_commit()
{
    asm volatile("cp.async.commit_group;");
}
__device__ __forceinline__ void cp_wait1()
{
    asm volatile("cp.async.wait_group 1;");
}

// ==============================================================================
// GEMM v5: cp.async double-buffered with 64-k stages (half the syncs of v4).
//   Compute tile = round-6 proven shape: warp = 4 m-rows, lane = n in
//   {tx, tx+32}; 68-float rows, conflict-free.
// ==============================================================================
__device__ __forceinline__ void gemm_pipe(
    const float* __restrict__ X, const float* __restrict__ W,
    float* __restrict__ out, int tile, int kbeg, int nstages)
{
    __shared__ __align__(16) float Xs[NST][32 * 68];
    __shared__ __align__(16) float Ws[NST][64 * 68];

    const int tid = threadIdx.x;
    const int tx = tid & 31;
    const int ty = tid >> 5;

    // X: 2 cp16/thread/stage (32 rows x 64 k)
    uint32_t xs_a[2];
    const float* xg[2];
#pragma unroll
    for (int i = 0; i < 2; i++) {
        const int fid = i * 256 + tid;
        const int xrow = fid >> 4, xc4 = fid & 15;
        xs_a[i] = (uint32_t)__cvta_generic_to_shared(
            &Xs[0][xrow * 68 + xc4 * 4]);
        xg[i] = X + (size_t)xrow * DMODEL + kbeg + xc4 * 4;
    }
    // W: 4 cp16/thread/stage (64 rows x 64 k)
    uint32_t ws_a[4];
    const float* wg[4];
#pragma unroll
    for (int i = 0; i < 4; i++) {
        const int fid = i * 256 + tid;
        const int wrow = fid >> 4, wc4 = fid & 15;
        ws_a[i] = (uint32_t)__cvta_generic_to_shared(
            &Ws[0][wrow * 68 + wc4 * 4]);
        wg[i] = W + (size_t)(tile * 64 + wrow) * DMODEL + kbeg + wc4 * 4;
    }
    const uint32_t XBUF = 32 * 68 * 4;
    const uint32_t WBUF = 64 * 68 * 4;

    unsigned long long acc[4][2];
#pragma unroll
    for (int i = 0; i < 4; i++) { acc[i][0] = 0ull; acc[i][1] = 0ull; }

    // prologue: issue stages 0..1
#pragma unroll
    for (int s = 0; s < NST; s++) {
#pragma unroll
        for (int i = 0; i < 2; i++) cp16(xs_a[i] + s * XBUF, xg[i] + s * 64);
#pragma unroll
        for (int i = 0; i < 4; i++) cp16(ws_a[i] + s * WBUF, wg[i] + s * 64);
        cp_commit();
    }

    for (int st = 0; st < nstages; ++st) {
        const int buf = st & 1;
        cp_wait1();                 // stage st arrived
        __syncthreads();

        const float* xb = Xs[buf];
        const float* wb = Ws[buf];
#pragma unroll
        for (int kk = 0; kk < 64; kk += 8) {
            F4 w00, w01, w10, w11;
            w00.v = *(const float4*)(wb + tx * 68 + kk);
            w01.v = *(const float4*)(wb + tx * 68 + kk + 4);
            w10.v = *(const float4*)(wb + (tx + 32) * 68 + kk);
            w11.v = *(const float4*)(wb + (tx + 32) * 68 + kk + 4);
#pragma unroll
            for (int i = 0; i < 4; i++) {
                F4 xa, xc;
                xa.v = *(const float4*)(xb + (ty * 4 + i) * 68 + kk);
                xc.v = *(const float4*)(xb + (ty * 4 + i) * 68 + kk + 4);
                ffma2(acc[i][0], xa.u[0], w00.u[0]);
                ffma2(acc[i][0], xa.u[1], w00.u[1]);
                ffma2(acc[i][0], xc.u[0], w01.u[0]);
                ffma2(acc[i][0], xc.u[1], w01.u[1]);
                ffma2(acc[i][1], xa.u[0], w10.u[0]);
                ffma2(acc[i][1], xa.u[1], w10.u[1]);
                ffma2(acc[i][1], xc.u[0], w11.u[0]);
                ffma2(acc[i][1], xc.u[1], w11.u[1]);
            }
        }
        __syncthreads();            // all warps done with buf before refill

        const int nx = st + NST;
        if (nx < nstages) {
#pragma unroll
            for (int i = 0; i < 2; i++) cp16(xs_a[i] + buf * XBUF, xg[i] + nx * 64);
#pragma unroll
            for (int i = 0; i < 4; i++) cp16(ws_a[i] + buf * WBUF, wg[i] + nx * 64);
        }
        cp_commit();                // one group/iter keeps counts aligned
    }

#pragma unroll
    for (int i = 0; i < 4; i++) {
#pragma unroll
        for (int j = 0; j < 2; j++) {
            const float2 h2 = unpack2(acc[i][j]);
            out[(size_t)(ty * 4 + i) * DMODEL + tile * 64 + tx + j * 32] =
                h2.x + h2.y;
        }
    }
}

// qkv: grid 768 = 3 mats x 8 splits x 32 tiles; 4 stages of 64 k per block
__global__ void __launch_bounds__(256, 3) qkv_gemm_kernel(
    const float* __restrict__ x,
    const float* __restrict__ wq, const float* __restrict__ wk,
    const float* __restrict__ wv)
{
    const int tile = blockIdx.x & 31;
    const int ks   = (blockIdx.x >> 5) & 7;
    const int g    = blockIdx.x >> 8;
    const float* W = (g == 0) ? wq : (g == 1 ? wk : wv);
    gemm_pipe(x, W, g_qkvp[g][ks], tile, ks * 256, 4);
}

// wo: grid 512 = 16 splits x 32 tiles; 2 stages of 64 k per block
__global__ void __launch_bounds__(256, 3) wo_gemm_kernel(const float* __restrict__ wo)
{
    const int ks = blockIdx.x >> 5;
    const int tile = blockIdx.x & 31;
    gemm_pipe(g_attn, wo, g_part[ks], tile, ks * 128, 2);
}

__global__ void __launch_bounds__(256) combine_kernel(float* __restrict__ out)
{
    const int i = blockIdx.x * 256 + threadIdx.x;
    float r = 0.f;
#pragma unroll
    for (int ks = 0; ks < WO_SPLIT; ks++) r += g_part[ks][i];
    out[i] = r;
}

// ==============================================================================
// Attention v8 (round-14 proven): fused single-pass QK -> exp -> AV,
//   no-max softmax, PF2 triple-buffered K/V prefetch.
// ==============================================================================
__global__ void __launch_bounds__(256, 2) attn_kernel(
    const float* __restrict__ ck, const float* __restrict__ cv,
    const float* __restrict__ fc, const float* __restrict__ fs)
{
    __shared__ __align__(16) float qs[4 * 68];
    __shared__ __align__(16) float kxs[4 * 68];
    __shared__ __align__(16) float vxs[4 * 68];
    __shared__ __align__(16) float avred[8 * 256];
    __shared__ __align__(16) float red[40];
    __shared__ __align__(16) float scnew[16];

    const int bh    = blockIdx.x >> 3;
    const int split = blockIdx.x & 7;
    const int b = bh >> 5;
    const int h = bh & 31;
    const int tid = threadIdx.x;
    const int kbase = split * KPB;
    const int wid = tid >> 5, lane = tid & 31;

    // prologue: combine qkv partials + RoPE
    if (tid < 128) {
        const int s = tid >> 5, p = tid & 31;
        const size_t off = (size_t)(b * SEQ + s) * DMODEL + h * HDIM + 2 * p;
        float2 e = *(const float2*)(&g_qkvp[0][0][off]);
#pragma unroll
        for (int ks = 1; ks < QKV_SPLIT; ks++) {
            const float2 t = *(const float2*)(&g_qkvp[0][ks][off]);
            e.x += t.x; e.y += t.y;
        }
        const float c  = fc[s * 32 + p];
        const float sn = fs[s * 32 + p];
        qs[s * 68 + 2 * p]     = (e.x * c - e.y * sn) * 0.125f;
        qs[s * 68 + 2 * p + 1] = (e.x * sn + e.y * c) * 0.125f;
    } else if (split == SPLIT - 1) {
        const int t2 = tid - 128;
        const int s = t2 >> 5, p = t2 & 31;
        const size_t off = (size_t)(b * SEQ + s) * DMODEL + h * HDIM + 2 * p;
        float2 e = *(const float2*)(&g_qkvp[1][0][off]);
#pragma unroll
        for (int ks = 1; ks < QKV_SPLIT; ks++) {
            const float2 t = *(const float2*)(&g_qkvp[1][ks][off]);
            e.x += t.x; e.y += t.y;
        }
        const float c  = fc[s * 32 + p];
        const float sn = fs[s * 32 + p];
        kxs[s * 68 + 2 * p]     = e.x * c - e.y * sn;
        kxs[s * 68 + 2 * p + 1] = e.x * sn + e.y * c;
        float2 v = *(const float2*)(&g_qkvp[2][0][off]);
#pragma unroll
        for (int ks = 1; ks < QKV_SPLIT; ks++) {
            const float2 t = *(const float2*)(&g_qkvp[2][ks][off]);
            v.x += t.x; v.y += t.y;
        }
        vxs[s * 68 + 2 * p]     = v.x;
        vxs[s * 68 + 2 * p + 1] = v.y;
    }
    __syncthreads();

    const int g = lane >> 3;
    const int s = lane & 7;

    F4 qr[4][2];
#pragma unroll
    for (int qi = 0; qi < 4; qi++) {
        qr[qi][0].v = *(const float4*)(qs + qi * 68 + s * 4);
        qr[qi][1].v = *(const float4*)(qs + qi * 68 + s * 4 + 32);
    }

    const size_t rs = NHEAD * HDIM;
    const size_t rowoff = ((size_t)b * CACHE * NHEAD + h) * HDIM
                        + (size_t)(kbase + wid * 64 + g) * rs + s * 4;
    const float* kp = ck + rowoff;
    const float* vp = cv + rowoff;

    unsigned long long acc[4][4];
#pragma unroll
    for (int q = 0; q < 4; q++)
#pragma unroll
        for (int j = 0; j < 4; j++) acc[q][j] = 0ull;
    float ssum = 0.f;

    // PF2 triple-buffered prefetch (8 LDG.128 in flight per thread)
    F4 kA[3][2], vA[3][2];
#pragma unroll
    for (int r = 0; r < 2; r++) {
        const float* kn = kp + (size_t)r * 4 * rs;
        const float* vn = vp + (size_t)r * 4 * rs;
        kA[r][0].v = *(const float4*)(kn);
        kA[r][1].v = *(const float4*)(kn + 32);
        vA[r][0].v = *(const float4*)(vn);
        vA[r][1].v = *(const float4*)(vn + 32);
    }

#pragma unroll
    for (int r = 0; r < 16; r++) {
        const int cur = r % 3;
        if (r + 2 < 16) {
            const int nxt = (r + 2) % 3;
            const float* kn = kp + (size_t)(r + 2) * 4 * rs;
            const float* vn = vp + (size_t)(r + 2) * 4 * rs;
            kA[nxt][0].v = *(const float4*)(kn);
            kA[nxt][1].v = *(const float4*)(kn + 32);
            vA[nxt][0].v = *(const float4*)(vn);
            vA[nxt][1].v = *(const float4*)(vn + 32);
        }

        float p0, p1, p2, p3;
        {
            unsigned long long a = 0ull;
            ffma2(a, kA[cur][0].u[0], qr[0][0].u[0]); ffma2(a, kA[cur][0].u[1], qr[0][0].u[1]);
            ffma2(a, kA[cur][1].u[0], qr[0][1].u[0]); ffma2(a, kA[cur][1].u[1], qr[0][1].u[1]);
            const float2 t = unpack2(a); p0 = t.x + t.y;
        }
        {
            unsigned long long a = 0ull;
            ffma2(a, kA[cur][0].u[0], qr[1][0].u[0]); ffma2(a, kA[cur][0].u[1], qr[1][0].u[1]);
            ffma2(a, kA[cur][1].u[0], qr[1][1].u[0]); ffma2(a, kA[cur][1].u[1], qr[1][1].u[1]);
            const float2 t = unpack2(a); p1 = t.x + t.y;
        }
        {
            unsigned long long a = 0ull;
            ffma2(a, kA[cur][0].u[0], qr[2][0].u[0]); ffma2(a, kA[cur][0].u[1], qr[2][0].u[1]);
            ffma2(a, kA[cur][1].u[0], qr[2][1].u[0]); ffma2(a, kA[cur][1].u[1], qr[2][1].u[1]);
            const float2 t = unpack2(a); p2 = t.x + t.y;
        }
        {
            unsigned long long a = 0ull;
            ffma2(a, kA[cur][0].u[0], qr[3][0].u[0]); ffma2(a, kA[cur][0].u[1], qr[3][0].u[1]);
            ffma2(a, kA[cur][1].u[0], qr[3][1].u[0]); ffma2(a, kA[cur][1].u[1], qr[3][1].u[1]);
            const float2 t = unpack2(a); p3 = t.x + t.y;
        }
#pragma unroll
        for (int o = 1; o <= 4; o <<= 1) {
            p0 += __shfl_xor_sync(0xffffffffu, p0, o);
            p1 += __shfl_xor_sync(0xffffffffu, p1, o);
            p2 += __shfl_xor_sync(0xffffffffu, p2, o);
            p3 += __shfl_xor_sync(0xffffffffu, p3, o);
        }
        const float e0 = __expf(p0);
        const float e1 = __expf(p1);
        const float e2 = __expf(p2);
        const float e3 = __expf(p3);
        {
            const float pa = (s & 1) ? e1 : e0;
            const float pb = (s & 1) ? e3 : e2;
            if (s < 4) ssum += (s & 2) ? pb : pa;
        }
        {
            const unsigned long long ee0 = pack2(e0, e0);
            const unsigned long long ee1 = pack2(e1, e1);
            const unsigned long long ee2 = pack2(e2, e2);
            const unsigned long long ee3 = pack2(e3, e3);
            ffma2(acc[0][0], vA[cur][0].u[0], ee0); ffma2(acc[0][1], vA[cur][0].u[1], ee0);
            ffma2(acc[0][2], vA[cur][1].u[0], ee0); ffma2(acc[0][3], vA[cur][1].u[1], ee0);
            ffma2(acc[1][0], vA[cur][0].u[0], ee1); ffma2(acc[1][1], vA[cur][0].u[1], ee1);
            ffma2(acc[1][2], vA[cur][1].u[0], ee1); ffma2(acc[1][3], vA[cur][1].u[1], ee1);
            ffma2(acc[2][0], vA[cur][0].u[0], ee2); ffma2(acc[2][1], vA[cur][0].u[1], ee2);
            ffma2(acc[2][2], vA[cur][1].u[0], ee2); ffma2(acc[2][3], vA[cur][1].u[1], ee2);
            ffma2(acc[3][0], vA[cur][0].u[0], ee3); ffma2(acc[3][1], vA[cur][0].u[1], ee3);
            ffma2(acc[3][2], vA[cur][1].u[0], ee3); ffma2(acc[3][3], vA[cur][1].u[1], ee3);
        }
    }

#pragma unroll
    for (int q = 0; q < 4; q++) {
        float o0 = unpack2(acc[q][0]).x, o1 = unpack2(acc[q][0]).y;
        float o2 = unpack2(acc[q][1]).x, o3 = unpack2(acc[q][1]).y;
        float o4 = unpack2(acc[q][2]).x, o5 = unpack2(acc[q][2]).y;
        float o6 = unpack2(acc[q][3]).x, o7 = unpack2(acc[q][3]).y;
#pragma unroll
        for (int o = 8; o <= 16; o <<= 1) {
            o0 += __shfl_xor_sync(0xffffffffu, o0, o);
            o1 += __shfl_xor_sync(0xffffffffu, o1, o);
            o2 += __shfl_xor_sync(0xffffffffu, o2, o);
            o3 += __shfl_xor_sync(0xffffffffu, o3, o);
            o4 += __shfl_xor_sync(0xffffffffu, o4, o);
            o5 += __shfl_xor_sync(0xffffffffu, o5, o);
            o6 += __shfl_xor_sync(0xffffffffu, o6, o);
            o7 += __shfl_xor_sync(0xffffffffu, o7, o);
        }
        if (g == 0) {
            *(float4*)(avred + wid * 256 + q * 64 + s * 4) =
                make_float4(o0, o1, o2, o3);
            *(float4*)(avred + wid * 256 + q * 64 + 32 + s * 4) =
                make_float4(o4, o5, o6, o7);
        }
    }
    ssum += __shfl_xor_sync(0xffffffffu, ssum, 8);
    ssum += __shfl_xor_sync(0xffffffffu, ssum, 16);
    if (lane < 4) red[wid * 4 + lane] = ssum;

    if (split == SPLIT - 1) {
        if (tid < 16) {
            const int q = tid >> 2, j = tid & 3;
            float a = 0.f;
#pragma unroll
            for (int d = 0; d < HDIM; d++) a += qs[q * 68 + d] * kxs[j * 68 + d];
            scnew[j * 4 + q] = (j > q) ? 0.f : __expf(a);
        }
    } else if (tid < 16) {
        scnew[tid] = 0.f;
    }
    __syncthreads();

    if (tid < 4) {
        float t = 0.f;
#pragma unroll
        for (int w = 0; w < 8; w++) t += red[w * 4 + tid];
#pragma unroll
        for (int j = 0; j < SEQ; j++) t += scnew[j * 4 + tid];
        red[32 + tid] = t;
    }
    __syncthreads();

    // write this split's unnormalized partial + s
    {
        const int q = tid >> 6, d = tid & 63;
        float r = 0.f;
#pragma unroll
        for (int w = 0; w < 8; w++) r += avred[w * 256 + q * 64 + d];
        if (split == SPLIT - 1) {
#pragma unroll
            for (int j = 0; j < SEQ; j++)
                r += scnew[j * 4 + q] * vxs[j * 68 + d];
        }
        const int base = (bh * SPLIT + split) * SEQ + q;
        g_po[(size_t)base * HDIM + d] = r;
        if (d == 0) g_s[base] = red[32 + q];
    }
}

// merge the 8 split partials per (b, h): pure sum
__global__ void __launch_bounds__(256) attn_combine_kernel()
{
    const int bh = blockIdx.x;
    const int tid = threadIdx.x;
    const int q = tid >> 6, d = tid & 63;

    float num = 0.f, den = 0.f;
#pragma unroll
    for (int i = 0; i < SPLIT; i++) {
        const int base = (bh * SPLIT + i) * SEQ + q;
        num += g_po[(size_t)base * HDIM + d];
        den += g_s[base];
    }
    const int b = bh >> 5, h = bh & 31;
    g_attn[(size_t)(b * SEQ + q) * DMODEL + h * HDIM + d] = num / den;
}

// ==============================================================================
extern "C" void kernel_launch(void* const* d_in, const int* in_sizes, int n_in,
                              void* d_out, int out_size)
{
    const float* x  = (const float*)d_in[0];
    const float* fc = (const float*)d_in[1];
    const float* fs = (const float*)d_in[2];
    const float* ck = (const float*)d_in[4];
    const float* cv = (const float*)d_in[5];
    const float* wq = (const float*)d_in[6];
    const float* wk = (const float*)d_in[7];
    const float* wv = (const float*)d_in[8];
    const float* wo = (const float*)d_in[9];
    float* out = (float*)d_out;

    qkv_gemm_kernel<<<3 * QKV_SPLIT * 32, 256>>>(x, wq, wk, wv);
    attn_kernel<<<BATCH * NHEAD * SPLIT, 256>>>(ck, cv, fc, fs);
    attn_combine_kernel<<<BATCH * NHEAD, 256>>>();
    wo_gemm_kernel<<<WO_SPLIT * 32, 256>>>(wo);
    combine_kernel<<<MROWS * DMODEL / 256, 256>>>(out);
}

// round 17
// speedup vs baseline: 1.0765x; 1.0446x over previous
#include <cuda_runtime.h>
#include <cstdint>

// Problem constants
#define BATCH 8
#define SEQ   4
#define DMODEL 2048
#define NHEAD 32
#define HDIM  64
#define CACHE 4096
#define MROWS (BATCH * SEQ)   // 32
#define SPLIT 8
#define KPB   512             // cache keys per attention block
#define QKV_SPLIT 8
#define WO_SPLIT  16
#define NST   2               // cp.async pipeline depth (64-k stages)

// ---------------- scratch (device globals; no allocation allowed) -------------
static __device__ float g_attn[MROWS * DMODEL];
static __device__ float g_qkvp[3][QKV_SPLIT][MROWS * DMODEL];
static __device__ float g_part[WO_SPLIT][MROWS * DMODEL];
static __device__ float g_po[BATCH * NHEAD * SPLIT * SEQ * HDIM];
static __device__ float g_s [BATCH * NHEAD * SPLIT * SEQ];

// ---------------- f32x2 helpers -----------------------------------------------
__device__ __forceinline__ void ffma2(unsigned long long& d,
                                      unsigned long long a,
                                      unsigned long long b)
{
    asm volatile("fma.rn.f32x2 %0, %1, %2, %0;" : "+l"(d) : "l"(a), "l"(b));
}
__device__ __forceinline__ float2 unpack2(unsigned long long u)
{
    float2 r;
    asm volatile("mov.b64 {%0, %1}, %2;" : "=f"(r.x), "=f"(r.y) : "l"(u));
    return r;
}
__device__ __forceinline__ unsigned long long pack2(float a, float b)
{
    unsigned long long u;
    asm volatile("mov.b64 %0, {%1, %2};" : "=l"(u) : "f"(a), "f"(b));
    return u;
}
union F4 { float4 v; unsigned long long u[2]; };

__device__ __forceinline__ void cp16(uint32_t smem_addr, const float* gptr)
{
    asm volatile("cp.async.cg.shared.global [%0], [%1], 16;"
                 :: "r"(smem_addr), "l"(gptr));
}
__device__ __forceinline__ void cp_commit()
{
    asm volatile("cp.async.commit_group;");
}
__device__ __forceinline__ void cp_wait1()
{
    asm volatile("cp.async.wait_group 1;");
}

// ==============================================================================
// GEMM v6: 128 threads, 4m x 4n register blocking (strided), 64-k cp.async
//   double-buffered stages. Thread (mg = t>>4, ng = t&15) owns
//   m in {mg + 8i}, n in {ng + 16j}. Bank math (68-float rows, quad = row%8):
//   X loads = 2-addr broadcast (1 wf), W loads = 16 rows over 8 quads (2 wf).
//   Per 4-k per warp: 12 wf vs 32 ffma2 -> FMA-bound.
// ==============================================================================
__device__ __forceinline__ void gemm_pipe(
    const float* __restrict__ X, const float* __restrict__ W,
    float* __restrict__ out, int tile, int kbeg, int nstages)
{
    __shared__ __align__(16) float Xs[NST][32 * 68];
    __shared__ __align__(16) float Ws[NST][64 * 68];

    const int tid = threadIdx.x;        // 0..127
    const int mg = tid >> 4;            // 0..7
    const int ng = tid & 15;            // 0..15

    // X: 4 cp16/thread/stage (32 rows x 64 k = 512 float4)
    uint32_t xs_a[4];
    const float* xg[4];
#pragma unroll
    for (int i = 0; i < 4; i++) {
        const int fid = i * 128 + tid;
        const int xrow = fid >> 4, xc4 = fid & 15;
        xs_a[i] = (uint32_t)__cvta_generic_to_shared(
            &Xs[0][xrow * 68 + xc4 * 4]);
        xg[i] = X + (size_t)xrow * DMODEL + kbeg + xc4 * 4;
    }
    // W: 8 cp16/thread/stage (64 rows x 64 k = 1024 float4)
    uint32_t ws_a[8];
    const float* wg[8];
#pragma unroll
    for (int i = 0; i < 8; i++) {
        const int fid = i * 128 + tid;
        const int wrow = fid >> 4, wc4 = fid & 15;
        ws_a[i] = (uint32_t)__cvta_generic_to_shared(
            &Ws[0][wrow * 68 + wc4 * 4]);
        wg[i] = W + (size_t)(tile * 64 + wrow) * DMODEL + kbeg + wc4 * 4;
    }
    const uint32_t XBUF = 32 * 68 * 4;
    const uint32_t WBUF = 64 * 68 * 4;

    unsigned long long acc[4][4];       // [i: m=mg+8i][j: n=ng+16j]
#pragma unroll
    for (int i = 0; i < 4; i++)
#pragma unroll
        for (int j = 0; j < 4; j++) acc[i][j] = 0ull;

    // prologue: issue stages 0..1
#pragma unroll
    for (int s = 0; s < NST; s++) {
#pragma unroll
        for (int i = 0; i < 4; i++) cp16(xs_a[i] + s * XBUF, xg[i] + s * 64);
#pragma unroll
        for (int i = 0; i < 8; i++) cp16(ws_a[i] + s * WBUF, wg[i] + s * 64);
        cp_commit();
    }

    for (int st = 0; st < nstages; ++st) {
        const int buf = st & 1;
        cp_wait1();                 // stage st arrived
        __syncthreads();

        const float* xb = Xs[buf];
        const float* wb = Ws[buf];
#pragma unroll
        for (int kk = 0; kk < 64; kk += 4) {
            F4 xv[4], wv[4];
#pragma unroll
            for (int i = 0; i < 4; i++)     // 2-addr broadcast, 1 wf
                xv[i].v = *(const float4*)(xb + (mg + 8 * i) * 68 + kk);
#pragma unroll
            for (int j = 0; j < 4; j++)     // 16 rows over 8 quads, 2 wf
                wv[j].v = *(const float4*)(wb + (ng + 16 * j) * 68 + kk);
#pragma unroll
            for (int i = 0; i < 4; i++)
#pragma unroll
                for (int j = 0; j < 4; j++) {
                    ffma2(acc[i][j], xv[i].u[0], wv[j].u[0]);
                    ffma2(acc[i][j], xv[i].u[1], wv[j].u[1]);
                }
        }
        __syncthreads();            // all warps done with buf before refill

        const int nx = st + NST;
        if (nx < nstages) {
#pragma unroll
            for (int i = 0; i < 4; i++) cp16(xs_a[i] + buf * XBUF, xg[i] + nx * 64);
#pragma unroll
            for (int i = 0; i < 8; i++) cp16(ws_a[i] + buf * WBUF, wg[i] + nx * 64);
        }
        cp_commit();                // one group/iter keeps counts aligned
    }

#pragma unroll
    for (int i = 0; i < 4; i++)
#pragma unroll
        for (int j = 0; j < 4; j++) {
            const float2 h2 = unpack2(acc[i][j]);
            out[(size_t)(mg + 8 * i) * DMODEL + tile * 64 + ng + 16 * j] =
                h2.x + h2.y;
        }
}

// qkv: grid 768 = 3 mats x 8 splits x 32 tiles; 4 stages of 64 k per block
__global__ void __launch_bounds__(128, 4) qkv_gemm_kernel(
    const float* __restrict__ x,
    const float* __restrict__ wq, const float* __restrict__ wk,
    const float* __restrict__ wv)
{
    const int tile = blockIdx.x & 31;
    const int ks   = (blockIdx.x >> 5) & 7;
    const int g    = blockIdx.x >> 8;
    const float* W = (g == 0) ? wq : (g == 1 ? wk : wv);
    gemm_pipe(x, W, g_qkvp[g][ks], tile, ks * 256, 4);
}

// wo: grid 512 = 16 splits x 32 tiles; 2 stages of 64 k per block
__global__ void __launch_bounds__(128, 4) wo_gemm_kernel(const float* __restrict__ wo)
{
    const int ks = blockIdx.x >> 5;
    const int tile = blockIdx.x & 31;
    gemm_pipe(g_attn, wo, g_part[ks], tile, ks * 128, 2);
}

__global__ void __launch_bounds__(256) combine_kernel(float* __restrict__ out)
{
    const int i = blockIdx.x * 256 + threadIdx.x;
    float r = 0.f;
#pragma unroll
    for (int ks = 0; ks < WO_SPLIT; ks++) r += g_part[ks][i];
    out[i] = r;
}

// ==============================================================================
// Attention v8 (round-14/16 proven): fused single-pass QK -> exp -> AV,
//   no-max softmax, PF2 triple-buffered K/V prefetch.
// ==============================================================================
__global__ void __launch_bounds__(256, 2) attn_kernel(
    const float* __restrict__ ck, const float* __restrict__ cv,
    const float* __restrict__ fc, const float* __restrict__ fs)
{
    __shared__ __align__(16) float qs[4 * 68];
    __shared__ __align__(16) float kxs[4 * 68];
    __shared__ __align__(16) float vxs[4 * 68];
    __shared__ __align__(16) float avred[8 * 256];
    __shared__ __align__(16) float red[40];
    __shared__ __align__(16) float scnew[16];

    const int bh    = blockIdx.x >> 3;
    const int split = blockIdx.x & 7;
    const int b = bh >> 5;
    const int h = bh & 31;
    const int tid = threadIdx.x;
    const int kbase = split * KPB;
    const int wid = tid >> 5, lane = tid & 31;

    // prologue: combine qkv partials + RoPE
    if (tid < 128) {
        const int s = tid >> 5, p = tid & 31;
        const size_t off = (size_t)(b * SEQ + s) * DMODEL + h * HDIM + 2 * p;
        float2 e = *(const float2*)(&g_qkvp[0][0][off]);
#pragma unroll
        for (int ks = 1; ks < QKV_SPLIT; ks++) {
            const float2 t = *(const float2*)(&g_qkvp[0][ks][off]);
            e.x += t.x; e.y += t.y;
        }
        const float c  = fc[s * 32 + p];
        const float sn = fs[s * 32 + p];
        qs[s * 68 + 2 * p]     = (e.x * c - e.y * sn) * 0.125f;
        qs[s * 68 + 2 * p + 1] = (e.x * sn + e.y * c) * 0.125f;
    } else if (split == SPLIT - 1) {
        const int t2 = tid - 128;
        const int s = t2 >> 5, p = t2 & 31;
        const size_t off = (size_t)(b * SEQ + s) * DMODEL + h * HDIM + 2 * p;
        float2 e = *(const float2*)(&g_qkvp[1][0][off]);
#pragma unroll
        for (int ks = 1; ks < QKV_SPLIT; ks++) {
            const float2 t = *(const float2*)(&g_qkvp[1][ks][off]);
            e.x += t.x; e.y += t.y;
        }
        const float c  = fc[s * 32 + p];
        const float sn = fs[s * 32 + p];
        kxs[s * 68 + 2 * p]     = e.x * c - e.y * sn;
        kxs[s * 68 + 2 * p + 1] = e.x * sn + e.y * c;
        float2 v = *(const float2*)(&g_qkvp[2][0][off]);
#pragma unroll
        for (int ks = 1; ks < QKV_SPLIT; ks++) {
            const float2 t = *(const float2*)(&g_qkvp[2][ks][off]);
            v.x += t.x; v.y += t.y;
        }
        vxs[s * 68 + 2 * p]     = v.x;
        vxs[s * 68 + 2 * p + 1] = v.y;
    }
    __syncthreads();

    const int g = lane >> 3;
    const int s = lane & 7;

    F4 qr[4][2];
#pragma unroll
    for (int qi = 0; qi < 4; qi++) {
        qr[qi][0].v = *(const float4*)(qs + qi * 68 + s * 4);
        qr[qi][1].v = *(const float4*)(qs + qi * 68 + s * 4 + 32);
    }

    const size_t rs = NHEAD * HDIM;
    const size_t rowoff = ((size_t)b * CACHE * NHEAD + h) * HDIM
                        + (size_t)(kbase + wid * 64 + g) * rs + s * 4;
    const float* kp = ck + rowoff;
    const float* vp = cv + rowoff;

    unsigned long long acc[4][4];
#pragma unroll
    for (int q = 0; q < 4; q++)
#pragma unroll
        for (int j = 0; j < 4; j++) acc[q][j] = 0ull;
    float ssum = 0.f;

    // PF2 triple-buffered prefetch (8 LDG.128 in flight per thread)
    F4 kA[3][2], vA[3][2];
#pragma unroll
    for (int r = 0; r < 2; r++) {
        const float* kn = kp + (size_t)r * 4 * rs;
        const float* vn = vp + (size_t)r * 4 * rs;
        kA[r][0].v = *(const float4*)(kn);
        kA[r][1].v = *(const float4*)(kn + 32);
        vA[r][0].v = *(const float4*)(vn);
        vA[r][1].v = *(const float4*)(vn + 32);
    }

#pragma unroll
    for (int r = 0; r < 16; r++) {
        const int cur = r % 3;
        if (r + 2 < 16) {
            const int nxt = (r + 2) % 3;
            const float* kn = kp + (size_t)(r + 2) * 4 * rs;
            const float* vn = vp + (size_t)(r + 2) * 4 * rs;
            kA[nxt][0].v = *(const float4*)(kn);
            kA[nxt][1].v = *(const float4*)(kn + 32);
            vA[nxt][0].v = *(const float4*)(vn);
            vA[nxt][1].v = *(const float4*)(vn + 32);
        }

        float p0, p1, p2, p3;
        {
            unsigned long long a = 0ull;
            ffma2(a, kA[cur][0].u[0], qr[0][0].u[0]); ffma2(a, kA[cur][0].u[1], qr[0][0].u[1]);
            ffma2(a, kA[cur][1].u[0], qr[0][1].u[0]); ffma2(a, kA[cur][1].u[1], qr[0][1].u[1]);
            const float2 t = unpack2(a); p0 = t.x + t.y;
        }
        {
            unsigned long long a = 0ull;
            ffma2(a, kA[cur][0].u[0], qr[1][0].u[0]); ffma2(a, kA[cur][0].u[1], qr[1][0].u[1]);
            ffma2(a, kA[cur][1].u[0], qr[1][1].u[0]); ffma2(a, kA[cur][1].u[1], qr[1][1].u[1]);
            const float2 t = unpack2(a); p1 = t.x + t.y;
        }
        {
            unsigned long long a = 0ull;
            ffma2(a, kA[cur][0].u[0], qr[2][0].u[0]); ffma2(a, kA[cur][0].u[1], qr[2][0].u[1]);
            ffma2(a, kA[cur][1].u[0], qr[2][1].u[0]); ffma2(a, kA[cur][1].u[1], qr[2][1].u[1]);
            const float2 t = unpack2(a); p2 = t.x + t.y;
        }
        {
            unsigned long long a = 0ull;
            ffma2(a, kA[cur][0].u[0], qr[3][0].u[0]); ffma2(a, kA[cur][0].u[1], qr[3][0].u[1]);
            ffma2(a, kA[cur][1].u[0], qr[3][1].u[0]); ffma2(a, kA[cur][1].u[1], qr[3][1].u[1]);
            const float2 t = unpack2(a); p3 = t.x + t.y;
        }
#pragma unroll
        for (int o = 1; o <= 4; o <<= 1) {
            p0 += __shfl_xor_sync(0xffffffffu, p0, o);
            p1 += __shfl_xor_sync(0xffffffffu, p1, o);
            p2 += __shfl_xor_sync(0xffffffffu, p2, o);
            p3 += __shfl_xor_sync(0xffffffffu, p3, o);
        }
        const float e0 = __expf(p0);
        const float e1 = __expf(p1);
        const float e2 = __expf(p2);
        const float e3 = __expf(p3);
        {
            const float pa = (s & 1) ? e1 : e0;
            const float pb = (s & 1) ? e3 : e2;
            if (s < 4) ssum += (s & 2) ? pb : pa;
        }
        {
            const unsigned long long ee0 = pack2(e0, e0);
            const unsigned long long ee1 = pack2(e1, e1);
            const unsigned long long ee2 = pack2(e2, e2);
            const unsigned long long ee3 = pack2(e3, e3);
            ffma2(acc[0][0], vA[cur][0].u[0], ee0); ffma2(acc[0][1], vA[cur][0].u[1], ee0);
            ffma2(acc[0][2], vA[cur][1].u[0], ee0); ffma2(acc[0][3], vA[cur][1].u[1], ee0);
            ffma2(acc[1][0], vA[cur][0].u[0], ee1); ffma2(acc[1][1], vA[cur][0].u[1], ee1);
            ffma2(acc[1][2], vA[cur][1].u[0], ee1); ffma2(acc[1][3], vA[cur][1].u[1], ee1);
            ffma2(acc[2][0], vA[cur][0].u[0], ee2); ffma2(acc[2][1], vA[cur][0].u[1], ee2);
            ffma2(acc[2][2], vA[cur][1].u[0], ee2); ffma2(acc[2][3], vA[cur][1].u[1], ee2);
            ffma2(acc[3][0], vA[cur][0].u[0], ee3); ffma2(acc[3][1], vA[cur][0].u[1], ee3);
            ffma2(acc[3][2], vA[cur][1].u[0], ee3); ffma2(acc[3][3], vA[cur][1].u[1], ee3);
        }
    }

#pragma unroll
    for (int q = 0; q < 4; q++) {
        float o0 = unpack2(acc[q][0]).x, o1 = unpack2(acc[q][0]).y;
        float o2 = unpack2(acc[q][1]).x, o3 = unpack2(acc[q][1]).y;
        float o4 = unpack2(acc[q][2]).x, o5 = unpack2(acc[q][2]).y;
        float o6 = unpack2(acc[q][3]).x, o7 = unpack2(acc[q][3]).y;
#pragma unroll
        for (int o = 8; o <= 16; o <<= 1) {
            o0 += __shfl_xor_sync(0xffffffffu, o0, o);
            o1 += __shfl_xor_sync(0xffffffffu, o1, o);
            o2 += __shfl_xor_sync(0xffffffffu, o2, o);
            o3 += __shfl_xor_sync(0xffffffffu, o3, o);
            o4 += __shfl_xor_sync(0xffffffffu, o4, o);
            o5 += __shfl_xor_sync(0xffffffffu, o5, o);
            o6 += __shfl_xor_sync(0xffffffffu, o6, o);
            o7 += __shfl_xor_sync(0xffffffffu, o7, o);
        }
        if (g == 0) {
            *(float4*)(avred + wid * 256 + q * 64 + s * 4) =
                make_float4(o0, o1, o2, o3);
            *(float4*)(avred + wid * 256 + q * 64 + 32 + s * 4) =
                make_float4(o4, o5, o6, o7);
        }
    }
    ssum += __shfl_xor_sync(0xffffffffu, ssum, 8);
    ssum += __shfl_xor_sync(0xffffffffu, ssum, 16);
    if (lane < 4) red[wid * 4 + lane] = ssum;

    if (split == SPLIT - 1) {
        if (tid < 16) {
            const int q = tid >> 2, j = tid & 3;
            float a = 0.f;
#pragma unroll
            for (int d = 0; d < HDIM; d++) a += qs[q * 68 + d] * kxs[j * 68 + d];
            scnew[j * 4 + q] = (j > q) ? 0.f : __expf(a);
        }
    } else if (tid < 16) {
        scnew[tid] = 0.f;
    }
    __syncthreads();

    if (tid < 4) {
        float t = 0.f;
#pragma unroll
        for (int w = 0; w < 8; w++) t += red[w * 4 + tid];
#pragma unroll
        for (int j = 0; j < SEQ; j++) t += scnew[j * 4 + tid];
        red[32 + tid] = t;
    }
    __syncthreads();

    // write this split's unnormalized partial + s
    {
        const int q = tid >> 6, d = tid & 63;
        float r = 0.f;
#pragma unroll
        for (int w = 0; w < 8; w++) r += avred[w * 256 + q * 64 + d];
        if (split == SPLIT - 1) {
#pragma unroll
            for (int j = 0; j < SEQ; j++)
                r += scnew[j * 4 + q] * vxs[j * 68 + d];
        }
        const int base = (bh * SPLIT + split) * SEQ + q;
        g_po[(size_t)base * HDIM + d] = r;
        if (d == 0) g_s[base] = red[32 + q];
    }
}

// merge the 8 split partials per (b, h): pure sum
__global__ void __launch_bounds__(256) attn_combine_kernel()
{
    const int bh = blockIdx.x;
    const int tid = threadIdx.x;
    const int q = tid >> 6, d = tid & 63;

    float num = 0.f, den = 0.f;
#pragma unroll
    for (int i = 0; i < SPLIT; i++) {
        const int base = (bh * SPLIT + i) * SEQ + q;
        num += g_po[(size_t)base * HDIM + d];
        den += g_s[base];
    }
    const int b = bh >> 5, h = bh & 31;
    g_attn[(size_t)(b * SEQ + q) * DMODEL + h * HDIM + d] = num / den;
}

// ==============================================================================
extern "C" void kernel_launch(void* const* d_in, const int* in_sizes, int n_in,
                              void* d_out, int out_size)
{
    const float* x  = (const float*)d_in[0];
    const float* fc = (const float*)d_in[1];
    const float* fs = (const float*)d_in[2];
    const float* ck = (const float*)d_in[4];
    const float* cv = (const float*)d_in[5];
    const float* wq = (const float*)d_in[6];
    const float* wk = (const float*)d_in[7];
    const float* wv = (const float*)d_in[8];
    const float* wo = (const float*)d_in[9];
    float* out = (float*)d_out;

    qkv_gemm_kernel<<<3 * QKV_SPLIT * 32, 128>>>(x, wq, wk, wv);
    attn_kernel<<<BATCH * NHEAD * SPLIT, 256>>>(ck, cv, fc, fs);
    attn_combine_kernel<<<BATCH * NHEAD, 256>>>();
    wo_gemm_kernel<<<WO_SPLIT * 32, 128>>>(wo);
    combine_kernel<<<MROWS * DMODEL / 256, 256>>>(out);
}